// round 10
// baseline (speedup 1.0000x reference)
#include <cuda_runtime.h>
#include <cstdint>

// Morton encode permutation: out[s, morton(i,j)] = in[s, i, j]
// x: (8, 64, 256, 256) fp32 -> 512 slices of 256x256.
//
// 16 elements/thread: low 4 morton bits = (j0,i0,j1,i1) -> a 4x4 input block
// (i%4==0, j%4==0). Per thread: 4x LDG.128 (rows i..i+3, cols j..j+3) and
// 4x dense STG.128. Warp = 512 consecutive morton = 16x32 tile, so EVERY load
// instruction covers exactly four completely-full 128B lines (vs 8 half-lines
// in the 8-elt/thread kernel). L2 hints as in best-so-far R6 config:
// loads evict_last, stores evict_first.

static constexpr int N = 256;
static constexpr int SLICE = N * N;              // 65536
static constexpr int EPT = 16;                   // morton elements per thread
static constexpr int THREADS_PER_SLICE = SLICE / EPT;   // 4096
static constexpr int TOTAL_THREADS = 8 * 64 * THREADS_PER_SLICE;  // 2,097,152

__device__ __forceinline__ unsigned deinterleave16(unsigned v) {
    v &= 0x5555u;
    v = (v | (v >> 1)) & 0x3333u;
    v = (v | (v >> 2)) & 0x0F0Fu;
    v = (v | (v >> 4)) & 0x00FFu;
    return v;
}

__device__ __forceinline__ float4 ld_hint(const float4* p, uint64_t pol) {
    float4 r;
    asm volatile("ld.global.L2::cache_hint.v4.f32 {%0,%1,%2,%3}, [%4], %5;"
                 : "=f"(r.x), "=f"(r.y), "=f"(r.z), "=f"(r.w)
                 : "l"(p), "l"(pol));
    return r;
}

__device__ __forceinline__ void st_hint(float4* p, float4 v, uint64_t pol) {
    asm volatile("st.global.L2::cache_hint.v4.f32 [%0], {%1,%2,%3,%4}, %5;"
                 :: "l"(p), "f"(v.x), "f"(v.y), "f"(v.z), "f"(v.w), "l"(pol)
                 : "memory");
}

__global__ void __launch_bounds__(256) morton_kernel(const float* __restrict__ in,
                                                     float* __restrict__ out) {
    unsigned t = blockIdx.x * blockDim.x + threadIdx.x;

    uint64_t pol_keep, pol_drop;
    asm volatile("createpolicy.fractional.L2::evict_last.b64 %0, 1.0;"  : "=l"(pol_keep));
    asm volatile("createpolicy.fractional.L2::evict_first.b64 %0, 1.0;" : "=l"(pol_drop));

    unsigned s = t >> 12;                                   // slice id (t / 4096)
    unsigned m = (t & (THREADS_PER_SLICE - 1u)) << 4;       // base morton, low 4 bits zero

    unsigned j = deinterleave16(m);        // j % 4 == 0
    unsigned i = deinterleave16(m >> 1);   // i % 4 == 0

    const float* base = in + (size_t)s * SLICE + (size_t)i * N + j;

    // 4 independent LDG.128: rows i..i+3, cols j..j+3
    float4 r0 = ld_hint(reinterpret_cast<const float4*>(base),         pol_keep);
    float4 r1 = ld_hint(reinterpret_cast<const float4*>(base + N),     pol_keep);
    float4 r2 = ld_hint(reinterpret_cast<const float4*>(base + 2 * N), pol_keep);
    float4 r3 = ld_hint(reinterpret_cast<const float4*>(base + 3 * N), pol_keep);

    // m_off = j0 + 2*i0 + 4*j1 + 8*i1: row r=(i1 i0), col c=(j1 j0)
    //  0:(0,0)  1:(0,1)  2:(1,0)  3:(1,1)   4:(0,2)  5:(0,3)  6:(1,2)  7:(1,3)
    //  8:(2,0)  9:(2,1) 10:(3,0) 11:(3,1)  12:(2,2) 13:(2,3) 14:(3,2) 15:(3,3)
    float4* ob = reinterpret_cast<float4*>(out + (size_t)t * EPT);
    st_hint(ob + 0, make_float4(r0.x, r0.y, r1.x, r1.y), pol_drop);
    st_hint(ob + 1, make_float4(r0.z, r0.w, r1.z, r1.w), pol_drop);
    st_hint(ob + 2, make_float4(r2.x, r2.y, r3.x, r3.y), pol_drop);
    st_hint(ob + 3, make_float4(r2.z, r2.w, r3.z, r3.w), pol_drop);
}

extern "C" void kernel_launch(void* const* d_in, const int* in_sizes, int n_in,
                              void* d_out, int out_size) {
    const float* in = (const float*)d_in[0];
    float* out = (float*)d_out;

    int block = 256;
    int grid = TOTAL_THREADS / block;            // 8192 blocks
    morton_kernel<<<grid, block>>>(in, out);
}

// round 11
// speedup vs baseline: 1.1268x; 1.1268x over previous
#include <cuda_runtime.h>
#include <cstdint>

// Morton encode permutation: out[s, morton(i,j)] = in[s, i, j]
// x: (8, 64, 256, 256) fp32. Final configuration: the measured-optimal
// 8-elements/thread structure (one 8-element Morton block per thread = two
// LDG.128 + two dense STG.128, maximum warp count), with L2 hints
// (loads evict_last / stores evict_first) — best measured: 40.5us kernel.
// Ten rounds of variants (more ILP, v8 accesses, smem staging, 16/32
// elt/thread tilings, fractional policies) all regressed; this part wants
// many small fine-grained warps. Only delta vs best: block 512 (same thread
// mapping, fewer CTA dispatches).

static constexpr int N = 256;
static constexpr int SLICE = N * N;          // 65536
static constexpr int ELEMS_PER_THREAD = 8;
static constexpr int THREADS_PER_SLICE = SLICE / ELEMS_PER_THREAD;  // 8192

__device__ __forceinline__ unsigned deinterleave16(unsigned v) {
    v &= 0x5555u;
    v = (v | (v >> 1)) & 0x3333u;
    v = (v | (v >> 2)) & 0x0F0Fu;
    v = (v | (v >> 4)) & 0x00FFu;
    return v;
}

__device__ __forceinline__ float4 ld_hint(const float4* p, uint64_t pol) {
    float4 r;
    asm volatile("ld.global.L2::cache_hint.v4.f32 {%0,%1,%2,%3}, [%4], %5;"
                 : "=f"(r.x), "=f"(r.y), "=f"(r.z), "=f"(r.w)
                 : "l"(p), "l"(pol));
    return r;
}

__device__ __forceinline__ void st_hint(float4* p, float4 v, uint64_t pol) {
    asm volatile("st.global.L2::cache_hint.v4.f32 [%0], {%1,%2,%3,%4}, %5;"
                 :: "l"(p), "f"(v.x), "f"(v.y), "f"(v.z), "f"(v.w), "l"(pol)
                 : "memory");
}

__global__ void __launch_bounds__(512) morton_kernel(const float* __restrict__ in,
                                                     float* __restrict__ out,
                                                     int total_threads) {
    int t = blockIdx.x * blockDim.x + threadIdx.x;
    if (t >= total_threads) return;

    uint64_t pol_keep, pol_drop;
    asm volatile("createpolicy.fractional.L2::evict_last.b64 %0, 1.0;"  : "=l"(pol_keep));
    asm volatile("createpolicy.fractional.L2::evict_first.b64 %0, 1.0;" : "=l"(pol_drop));

    unsigned s = (unsigned)t >> 13;                              // slice id
    unsigned m = ((unsigned)t & (THREADS_PER_SLICE - 1)) << 3;   // base morton index

    unsigned j = deinterleave16(m);        // j % 4 == 0
    unsigned i = deinterleave16(m >> 1);   // i % 2 == 0

    const float* slice_in = in + (size_t)s * SLICE;
    const float4* p = reinterpret_cast<const float4*>(slice_in + (size_t)i * N + j);
    float4 a = ld_hint(p, pol_keep);
    float4 b = ld_hint(p + N / 4, pol_keep);

    float4* ob = reinterpret_cast<float4*>(out + (size_t)t * ELEMS_PER_THREAD);
    // m+0:(i,j) m+1:(i,j+1) m+2:(i+1,j) m+3:(i+1,j+1)
    // m+4:(i,j+2) m+5:(i,j+3) m+6:(i+1,j+2) m+7:(i+1,j+3)
    st_hint(ob,     make_float4(a.x, a.y, b.x, b.y), pol_drop);
    st_hint(ob + 1, make_float4(a.z, a.w, b.z, b.w), pol_drop);
}

extern "C" void kernel_launch(void* const* d_in, const int* in_sizes, int n_in,
                              void* d_out, int out_size) {
    const float* in = (const float*)d_in[0];
    float* out = (float*)d_out;

    int total_elems = in_sizes[0];                       // 33,554,432
    int total_threads = total_elems / ELEMS_PER_THREAD;  // 4,194,304

    int block = 512;
    int grid = (total_threads + block - 1) / block;      // 8192
    morton_kernel<<<grid, block>>>(in, out, total_threads);
}

// round 12
// speedup vs baseline: 1.1276x; 1.0007x over previous
#include <cuda_runtime.h>
#include <cstdint>

// Morton encode permutation: out[s, morton(i,j)] = in[s, i, j]
// x: (8, 64, 256, 256) fp32. Final configuration: the measured-optimal
// 8-elements/thread structure (one 8-element Morton block per thread = two
// LDG.128 + two dense STG.128, maximum warp count), with L2 hints
// (loads evict_last / stores evict_first) — best measured: 40.5us kernel.
// Ten rounds of variants (more ILP, v8 accesses, smem staging, 16/32
// elt/thread tilings, fractional policies) all regressed; this part wants
// many small fine-grained warps. Only delta vs best: block 512 (same thread
// mapping, fewer CTA dispatches).

static constexpr int N = 256;
static constexpr int SLICE = N * N;          // 65536
static constexpr int ELEMS_PER_THREAD = 8;
static constexpr int THREADS_PER_SLICE = SLICE / ELEMS_PER_THREAD;  // 8192

__device__ __forceinline__ unsigned deinterleave16(unsigned v) {
    v &= 0x5555u;
    v = (v | (v >> 1)) & 0x3333u;
    v = (v | (v >> 2)) & 0x0F0Fu;
    v = (v | (v >> 4)) & 0x00FFu;
    return v;
}

__device__ __forceinline__ float4 ld_hint(const float4* p, uint64_t pol) {
    float4 r;
    asm volatile("ld.global.L2::cache_hint.v4.f32 {%0,%1,%2,%3}, [%4], %5;"
                 : "=f"(r.x), "=f"(r.y), "=f"(r.z), "=f"(r.w)
                 : "l"(p), "l"(pol));
    return r;
}

__device__ __forceinline__ void st_hint(float4* p, float4 v, uint64_t pol) {
    asm volatile("st.global.L2::cache_hint.v4.f32 [%0], {%1,%2,%3,%4}, %5;"
                 :: "l"(p), "f"(v.x), "f"(v.y), "f"(v.z), "f"(v.w), "l"(pol)
                 : "memory");
}

__global__ void __launch_bounds__(512) morton_kernel(const float* __restrict__ in,
                                                     float* __restrict__ out,
                                                     int total_threads) {
    int t = blockIdx.x * blockDim.x + threadIdx.x;
    if (t >= total_threads) return;

    uint64_t pol_keep, pol_drop;
    asm volatile("createpolicy.fractional.L2::evict_last.b64 %0, 1.0;"  : "=l"(pol_keep));
    asm volatile("createpolicy.fractional.L2::evict_first.b64 %0, 1.0;" : "=l"(pol_drop));

    unsigned s = (unsigned)t >> 13;                              // slice id
    unsigned m = ((unsigned)t & (THREADS_PER_SLICE - 1)) << 3;   // base morton index

    unsigned j = deinterleave16(m);        // j % 4 == 0
    unsigned i = deinterleave16(m >> 1);   // i % 2 == 0

    const float* slice_in = in + (size_t)s * SLICE;
    const float4* p = reinterpret_cast<const float4*>(slice_in + (size_t)i * N + j);
    float4 a = ld_hint(p, pol_keep);
    float4 b = ld_hint(p + N / 4, pol_keep);

    float4* ob = reinterpret_cast<float4*>(out + (size_t)t * ELEMS_PER_THREAD);
    // m+0:(i,j) m+1:(i,j+1) m+2:(i+1,j) m+3:(i+1,j+1)
    // m+4:(i,j+2) m+5:(i,j+3) m+6:(i+1,j+2) m+7:(i+1,j+3)
    st_hint(ob,     make_float4(a.x, a.y, b.x, b.y), pol_drop);
    st_hint(ob + 1, make_float4(a.z, a.w, b.z, b.w), pol_drop);
}

extern "C" void kernel_launch(void* const* d_in, const int* in_sizes, int n_in,
                              void* d_out, int out_size) {
    const float* in = (const float*)d_in[0];
    float* out = (float*)d_out;

    int total_elems = in_sizes[0];                       // 33,554,432
    int total_threads = total_elems / ELEMS_PER_THREAD;  // 4,194,304

    int block = 512;
    int grid = (total_threads + block - 1) / block;      // 8192
    morton_kernel<<<grid, block>>>(in, out, total_threads);
}